// round 1
// baseline (speedup 1.0000x reference)
#include <cuda_runtime.h>
#include <math.h>

// Problem constants (fixed by dataset)
#define S_SCENES 128
#define N_PED    64
#define HID      128
#define TOTAL    (S_SCENES * N_PED)   // 8192
#define QSCALE   0.17677669529663687f // 1/sqrt(32)

// ---------------- device scratch (static allocation, allowed) ----------------
__device__ float g_y[TOTAL * 384];    // q | kf | vf  (q pre-scaled)
__device__ float g_ctx[TOTAL * HID];  // attention context
__device__ float g_wk2[HID * 64];     // Wk @ W2
__device__ float g_wv2[HID * 64];     // Wv @ W2
__device__ float g_wco[HID * HID];    // P2 @ out_w
__device__ float g_bias384[384];      // [bq | bk+Wk@b2 | bv+Wv@b2]
__device__ float g_bco[HID];          // proj_b + P2 @ out_b

// ---------------- K1: combine weights ----------------
// total outputs: 384 + 8192 + 8192 + 16384 + 128 = 33280
__global__ void prep_kernel(const float* __restrict__ ipw,  // (384,128)
                            const float* __restrict__ ipb,  // (384,)
                            const float* __restrict__ W2,   // (128,64)
                            const float* __restrict__ b2,   // (128,)
                            const float* __restrict__ outw, // (128,128)
                            const float* __restrict__ outb, // (128,)
                            const float* __restrict__ pw,   // (128,256)
                            const float* __restrict__ pb)   // (128,)
{
    int idx = blockIdx.x * blockDim.x + threadIdx.x;
    if (idx < 384) {
        float v = ipb[idx];
        if (idx >= 128) {
            const float* wrow = ipw + idx * 128;
            float acc = 0.f;
            #pragma unroll 8
            for (int d = 0; d < 128; d++) acc += wrow[d] * b2[d];
            v += acc;
        }
        g_bias384[idx] = v;
        return;
    }
    int t = idx - 384;
    if (t < 8192) { // Wk2[hd][c]
        int hd = t >> 6, c = t & 63;
        const float* wrow = ipw + (128 + hd) * 128;
        float acc = 0.f;
        #pragma unroll 8
        for (int d = 0; d < 128; d++) acc += wrow[d] * W2[d * 64 + c];
        g_wk2[t] = acc;
        return;
    }
    t -= 8192;
    if (t < 8192) { // Wv2[hd][c]
        int hd = t >> 6, c = t & 63;
        const float* wrow = ipw + (256 + hd) * 128;
        float acc = 0.f;
        #pragma unroll 8
        for (int d = 0; d < 128; d++) acc += wrow[d] * W2[d * 64 + c];
        g_wv2[t] = acc;
        return;
    }
    t -= 8192;
    if (t < 16384) { // Wco[n][k] = sum_d P2[n][d]*out_w[d][k]
        int n = t >> 7, k = t & 127;
        const float* p2 = pw + n * 256 + 128;
        float acc = 0.f;
        #pragma unroll 8
        for (int d = 0; d < 128; d++) acc += p2[d] * outw[d * 128 + k];
        g_wco[t] = acc;
        return;
    }
    t -= 16384;
    if (t < 128) { // bco
        const float* p2 = pw + t * 256 + 128;
        float acc = pb[t];
        #pragma unroll 8
        for (int d = 0; d < 128; d++) acc += p2[d] * outb[d];
        g_bco[t] = acc;
    }
}

// ---------------- G1: Y = X @ in_proj_w^T + bias384; q block scaled ----------------
// M=8192, N=384, K=128. Tiles 64x64, BK=32, 256 threads, 4x4 microtile.
__global__ void __launch_bounds__(256) qkv_gemm(const float* __restrict__ X,
                                                const float* __restrict__ W)
{
    __shared__ float Xs[32][65];
    __shared__ float Ws[32][65];
    int m0 = blockIdx.x * 64, n0 = blockIdx.y * 64;
    int tid = threadIdx.x;
    int tx = tid & 15, ty = tid >> 4;
    float acc[4][4] = {};
    for (int k0 = 0; k0 < 128; k0 += 32) {
        for (int i = tid; i < 64 * 32; i += 256) {
            int m = i >> 5, k = i & 31;
            Xs[k][m] = X[(m0 + m) * 128 + k0 + k];
        }
        for (int i = tid; i < 64 * 32; i += 256) {
            int n = i >> 5, k = i & 31;
            Ws[k][n] = W[(n0 + n) * 128 + k0 + k];
        }
        __syncthreads();
        #pragma unroll 8
        for (int k = 0; k < 32; k++) {
            float a[4], b[4];
            #pragma unroll
            for (int r = 0; r < 4; r++) a[r] = Xs[k][ty * 4 + r];
            #pragma unroll
            for (int r = 0; r < 4; r++) b[r] = Ws[k][tx * 4 + r];
            #pragma unroll
            for (int r = 0; r < 4; r++)
                #pragma unroll
                for (int c = 0; c < 4; c++) acc[r][c] += a[r] * b[c];
        }
        __syncthreads();
    }
    #pragma unroll
    for (int r = 0; r < 4; r++)
        #pragma unroll
        for (int c = 0; c < 4; c++) {
            int m = m0 + ty * 4 + r, n = n0 + tx * 4 + c;
            float v = acc[r][c] + g_bias384[n];
            if (n < 128) v *= QSCALE;
            g_y[m * 384 + n] = v;
        }
}

// ---------------- K3: per-scene attention core ----------------
// 1 CTA per scene, 512 threads (16 warps), one warp processes one query i at a time.
// Dynamic smem layout (floats):
//  Q[64*128], KFt[128*65], VFt[128*65], WK2[128*64], WV2[128*65],
//  w1x[64], w1y[64], b1[64], px[64], py[64], Tw[16*256], SC[16*256], Gw[16*256]
#define ATTN_SMEM_FLOATS (8192 + 8320 + 8320 + 8192 + 8320 + 320 + 3 * 4096)

__global__ void __launch_bounds__(512) attn_kernel(const float* __restrict__ pos,
                                                   const float* __restrict__ W1,
                                                   const float* __restrict__ b1)
{
    extern __shared__ float sm[];
    float* Q   = sm;            // [64][128]
    float* KFt = Q + 8192;      // [128][65] transposed, padded
    float* VFt = KFt + 8320;    // [128][65]
    float* WK2 = VFt + 8320;    // [128][64] contiguous
    float* WV2 = WK2 + 8192;    // [128][65] padded
    float* w1x = WV2 + 8320;
    float* w1y = w1x + 64;
    float* b1s = w1y + 64;
    float* px  = b1s + 64;
    float* py  = px + 64;
    float* Tw  = py + 64;       // [16][256]
    float* SC  = Tw + 4096;     // [16][4][64]
    float* Gw  = SC + 4096;     // [16][256]

    int s = blockIdx.x;
    int tid = threadIdx.x;
    int w = tid >> 5, lane = tid & 31;
    int base = s * 64;

    for (int i = tid; i < 64 * 128; i += 512) {
        int r = i >> 7, c = i & 127;
        Q[i] = g_y[(base + r) * 384 + c];
        KFt[c * 65 + r] = g_y[(base + r) * 384 + 128 + c];
        VFt[c * 65 + r] = g_y[(base + r) * 384 + 256 + c];
    }
    for (int i = tid; i < 8192; i += 512) {
        WK2[i] = g_wk2[i];
        int hd = i >> 6, c = i & 63;
        WV2[hd * 65 + c] = g_wv2[i];
    }
    if (tid < 64) {
        w1x[tid] = W1[tid * 2 + 0];
        w1y[tid] = W1[tid * 2 + 1];
        b1s[tid] = b1[tid];
        px[tid]  = pos[(base + tid) * 2 + 0];
        py[tid]  = pos[(base + tid) * 2 + 1];
    }
    __syncthreads();

    float* myT  = Tw + w * 256;
    float* mySC = SC + w * 256;
    float* myG  = Gw + w * 256;

    float w1x0 = w1x[lane], w1x1 = w1x[lane + 32];
    float w1y0 = w1y[lane], w1y1 = w1y[lane + 32];
    float b10  = b1s[lane], b11  = b1s[lane + 32];

    for (int i = w; i < 64; i += 16) {
        const float* qrow = Q + i * 128;
        float pxi = px[i], pyi = py[i];

        // ---- t[h][c] = sum_d q[i][h*32+d] * Wk2[h*32+d][c]  (lanes over c) ----
        {
            float t0[4] = {0, 0, 0, 0}, t1[4] = {0, 0, 0, 0};
            #pragma unroll
            for (int h = 0; h < 4; h++) {
                #pragma unroll 8
                for (int d = 0; d < 32; d++) {
                    float qv = qrow[h * 32 + d];
                    const float* wr = WK2 + (h * 32 + d) * 64;
                    t0[h] += qv * wr[lane];
                    t1[h] += qv * wr[lane + 32];
                }
            }
            #pragma unroll
            for (int h = 0; h < 4; h++) {
                myT[h * 64 + lane]      = t0[h];
                myT[h * 64 + lane + 32] = t1[h];
            }
        }
        __syncwarp();

        // ---- scores + softmax (lanes over j: j0=lane, j1=lane+32) ----
        {
            int j0 = lane, j1 = lane + 32;
            float a0[4] = {0, 0, 0, 0}, a1[4] = {0, 0, 0, 0};
            #pragma unroll
            for (int h = 0; h < 4; h++) {
                #pragma unroll 8
                for (int d = 0; d < 32; d++) {
                    float qv = qrow[h * 32 + d];
                    const float* kr = KFt + (h * 32 + d) * 65;
                    a0[h] += qv * kr[j0];
                    a1[h] += qv * kr[j1];
                }
            }
            float dx0 = px[j0] - pxi, dy0 = py[j0] - pyi;
            float dx1 = px[j1] - pxi, dy1 = py[j1] - pyi;
            #pragma unroll 4
            for (int c = 0; c < 64; c++) {
                float h0 = fmaxf(w1x[c] * dx0 + w1y[c] * dy0 + b1s[c], 0.f);
                float h1 = fmaxf(w1x[c] * dx1 + w1y[c] * dy1 + b1s[c], 0.f);
                #pragma unroll
                for (int h = 0; h < 4; h++) {
                    float tv = myT[h * 64 + c];
                    a0[h] += tv * h0;
                    a1[h] += tv * h1;
                }
            }
            #pragma unroll
            for (int h = 0; h < 4; h++) {
                float m = fmaxf(a0[h], a1[h]);
                #pragma unroll
                for (int off = 16; off; off >>= 1)
                    m = fmaxf(m, __shfl_xor_sync(0xffffffffu, m, off));
                float e0 = __expf(a0[h] - m), e1 = __expf(a1[h] - m);
                float ssum = e0 + e1;
                #pragma unroll
                for (int off = 16; off; off >>= 1)
                    ssum += __shfl_xor_sync(0xffffffffu, ssum, off);
                float r = 1.f / ssum;
                mySC[h * 64 + j0] = e0 * r;
                mySC[h * 64 + j1] = e1 * r;
            }
        }
        __syncwarp();

        // ---- g[h][c] = sum_j attn[j][h] * hid[j][c]  (lanes over c, hid recomputed) ----
        {
            float g0[4] = {0, 0, 0, 0}, g1[4] = {0, 0, 0, 0};
            #pragma unroll 4
            for (int j = 0; j < 64; j++) {
                float dx = px[j] - pxi, dy = py[j] - pyi;
                float h0 = fmaxf(w1x0 * dx + w1y0 * dy + b10, 0.f);
                float h1 = fmaxf(w1x1 * dx + w1y1 * dy + b11, 0.f);
                #pragma unroll
                for (int h = 0; h < 4; h++) {
                    float a = mySC[h * 64 + j];
                    g0[h] += a * h0;
                    g1[h] += a * h1;
                }
            }
            #pragma unroll
            for (int h = 0; h < 4; h++) {
                myG[h * 64 + lane]      = g0[h];
                myG[h * 64 + lane + 32] = g1[h];
            }
        }
        __syncwarp();

        // ---- ctx[i][h*32+lane] = attn@vf + g@Wv2^T ----
        {
            #pragma unroll
            for (int h = 0; h < 4; h++) {
                float acc = 0.f;
                const float* vr = VFt + (h * 32 + lane) * 65;
                const float* ar = mySC + h * 64;
                #pragma unroll 8
                for (int j = 0; j < 64; j++) acc += ar[j] * vr[j];
                const float* wr = WV2 + (h * 32 + lane) * 65;
                const float* gr = myG + h * 64;
                #pragma unroll 8
                for (int c = 0; c < 64; c++) acc += gr[c] * wr[c];
                g_ctx[(base + i) * 128 + h * 32 + lane] = acc;
            }
        }
        __syncwarp();
    }
}

// ---------------- G2: OUT = X @ P1^T + CTX @ Wco^T + bco ----------------
// M=8192, N=128. Same tiling as G1, two accumulation passes.
__global__ void __launch_bounds__(256) out_gemm(const float* __restrict__ X,
                                                const float* __restrict__ PW,
                                                float* __restrict__ OUT)
{
    __shared__ float As[32][65];
    __shared__ float Bs[32][65];
    int m0 = blockIdx.x * 64, n0 = blockIdx.y * 64;
    int tid = threadIdx.x;
    int tx = tid & 15, ty = tid >> 4;
    float acc[4][4] = {};
    for (int phase = 0; phase < 2; phase++) {
        const float* A = phase ? g_ctx : X;
        for (int k0 = 0; k0 < 128; k0 += 32) {
            for (int i = tid; i < 64 * 32; i += 256) {
                int m = i >> 5, k = i & 31;
                As[k][m] = A[(m0 + m) * 128 + k0 + k];
            }
            for (int i = tid; i < 64 * 32; i += 256) {
                int n = i >> 5, k = i & 31;
                float wv = phase ? g_wco[(n0 + n) * 128 + k0 + k]
                                 : PW[(n0 + n) * 256 + k0 + k];
                Bs[k][n] = wv;
            }
            __syncthreads();
            #pragma unroll 8
            for (int k = 0; k < 32; k++) {
                float a[4], b[4];
                #pragma unroll
                for (int r = 0; r < 4; r++) a[r] = As[k][ty * 4 + r];
                #pragma unroll
                for (int r = 0; r < 4; r++) b[r] = Bs[k][tx * 4 + r];
                #pragma unroll
                for (int r = 0; r < 4; r++)
                    #pragma unroll
                    for (int c = 0; c < 4; c++) acc[r][c] += a[r] * b[c];
            }
            __syncthreads();
        }
    }
    #pragma unroll
    for (int r = 0; r < 4; r++)
        #pragma unroll
        for (int c = 0; c < 4; c++) {
            int m = m0 + ty * 4 + r, n = n0 + tx * 4 + c;
            OUT[m * 128 + n] = acc[r][c] + g_bco[n];
        }
}

// ---------------- launch ----------------
extern "C" void kernel_launch(void* const* d_in, const int* in_sizes, int n_in,
                              void* d_out, int out_size)
{
    const float* node_features = (const float*)d_in[0];   // (8192,128)
    const float* positions     = (const float*)d_in[1];   // (8192,2)
    const float* W1            = (const float*)d_in[2];   // (64,2)
    const float* b1            = (const float*)d_in[3];   // (64,)
    const float* W2            = (const float*)d_in[4];   // (128,64)
    const float* b2            = (const float*)d_in[5];   // (128,)
    const float* in_proj_w     = (const float*)d_in[6];   // (384,128)
    const float* in_proj_b     = (const float*)d_in[7];   // (384,)
    const float* out_w         = (const float*)d_in[8];   // (128,128)
    const float* out_b         = (const float*)d_in[9];   // (128,)
    const float* proj_w        = (const float*)d_in[10];  // (128,256)
    const float* proj_b        = (const float*)d_in[11];  // (128,)
    float* out = (float*)d_out;

    size_t attn_smem = (size_t)ATTN_SMEM_FLOATS * sizeof(float);
    cudaFuncSetAttribute(attn_kernel, cudaFuncAttributeMaxDynamicSharedMemorySize,
                         (int)attn_smem);

    prep_kernel<<<130, 256>>>(in_proj_w, in_proj_b, W2, b2, out_w, out_b, proj_w, proj_b);
    qkv_gemm<<<dim3(TOTAL / 64, 384 / 64), 256>>>(node_features, in_proj_w);
    attn_kernel<<<S_SCENES, 512, attn_smem>>>(positions, W1, b1);
    out_gemm<<<dim3(TOTAL / 64, 128 / 64), 256>>>(node_features, proj_w, out);
}

// round 2
// speedup vs baseline: 1.2618x; 1.2618x over previous
#include <cuda_runtime.h>
#include <math.h>

#define S_SCENES 128
#define N_PED    64
#define HID      128
#define TOTAL    (S_SCENES * N_PED)   // 8192
#define QSCALE   0.17677669529663687f // 1/sqrt(32)

// ---------------- device scratch ----------------
__device__ float g_y[TOTAL * 384];    // q | kf | vf  (q pre-scaled)
__device__ float g_ctx[TOTAL * HID];  // attention context
__device__ float g_wk2[HID * 64];     // Wk @ W2
__device__ float g_wv2[HID * 64];     // Wv @ W2
__device__ float g_wco[HID * HID];    // P2 @ out_w
__device__ float g_bias384[384];      // [bq | bk+Wk@b2 | bv+Wv@b2]
__device__ float g_bco[HID];          // proj_b + P2 @ out_b

// ---------------- f32x2 helpers ----------------
__device__ __forceinline__ unsigned long long dup2(float x) {
    unsigned long long r;
    asm("mov.b64 %0, {%1, %1};" : "=l"(r) : "r"(__float_as_uint(x)));
    return r;
}
__device__ __forceinline__ void ffma2(unsigned long long& d,
                                      unsigned long long a, unsigned long long b) {
    asm("fma.rn.f32x2 %0, %1, %2, %0;" : "+l"(d) : "l"(a), "l"(b));
}
__device__ __forceinline__ float2 unpk2(unsigned long long v) {
    unsigned lo, hi;
    asm("mov.b64 {%0, %1}, %2;" : "=r"(lo), "=r"(hi) : "l"(v));
    return make_float2(__uint_as_float(lo), __uint_as_float(hi));
}
union F4U { float4 f4; unsigned long long u[2]; float f[4]; };

// ---------------- K1: combine weights (unchanged) ----------------
__global__ void prep_kernel(const float* __restrict__ ipw,  // (384,128)
                            const float* __restrict__ ipb,  // (384,)
                            const float* __restrict__ W2,   // (128,64)
                            const float* __restrict__ b2,   // (128,)
                            const float* __restrict__ outw, // (128,128)
                            const float* __restrict__ outb, // (128,)
                            const float* __restrict__ pw,   // (128,256)
                            const float* __restrict__ pb)   // (128,)
{
    int idx = blockIdx.x * blockDim.x + threadIdx.x;
    if (idx < 384) {
        float v = ipb[idx];
        if (idx >= 128) {
            const float* wrow = ipw + idx * 128;
            float acc = 0.f;
            #pragma unroll 8
            for (int d = 0; d < 128; d++) acc += wrow[d] * b2[d];
            v += acc;
        }
        g_bias384[idx] = v;
        return;
    }
    int t = idx - 384;
    if (t < 8192) {
        int hd = t >> 6, c = t & 63;
        const float* wrow = ipw + (128 + hd) * 128;
        float acc = 0.f;
        #pragma unroll 8
        for (int d = 0; d < 128; d++) acc += wrow[d] * W2[d * 64 + c];
        g_wk2[t] = acc;
        return;
    }
    t -= 8192;
    if (t < 8192) {
        int hd = t >> 6, c = t & 63;
        const float* wrow = ipw + (256 + hd) * 128;
        float acc = 0.f;
        #pragma unroll 8
        for (int d = 0; d < 128; d++) acc += wrow[d] * W2[d * 64 + c];
        g_wv2[t] = acc;
        return;
    }
    t -= 8192;
    if (t < 16384) {
        int n = t >> 7, k = t & 127;
        const float* p2 = pw + n * 256 + 128;
        float acc = 0.f;
        #pragma unroll 8
        for (int d = 0; d < 128; d++) acc += p2[d] * outw[d * 128 + k];
        g_wco[t] = acc;
        return;
    }
    t -= 16384;
    if (t < 128) {
        const float* p2 = pw + t * 256 + 128;
        float acc = pb[t];
        #pragma unroll 8
        for (int d = 0; d < 128; d++) acc += p2[d] * outb[d];
        g_bco[t] = acc;
    }
}

// ---------------- GEMM core (shared by G1/G2) ----------------
// 128x64 tile, BK=32, 256 threads, 8x4 microtile via f32x2 (r-paired accs).
#define AS_P 132
#define BS_P 68

// ---------------- G1: Y = X @ in_proj_w^T + bias384; q block scaled ----------------
__global__ void __launch_bounds__(256) qkv_gemm(const float* __restrict__ X,
                                                const float* __restrict__ W)
{
    __shared__ float As[32][AS_P];   // [k][m]
    __shared__ float Bs[32][BS_P];   // [k][n]
    int m0 = blockIdx.x * 128, n0 = blockIdx.y * 64;
    int tid = threadIdx.x, tx = tid & 15, ty = tid >> 4;

    unsigned long long acc[4][4];
    #pragma unroll
    for (int r = 0; r < 4; r++)
        #pragma unroll
        for (int c = 0; c < 4; c++) acc[r][c] = 0ULL;

    float4 pa[4], pb[2];
    int rowA[4], kqA[4], rowB[2], kqB[2];
    #pragma unroll
    for (int i = 0; i < 4; i++) { int idx = tid + i * 256; rowA[i] = idx >> 3; kqA[i] = idx & 7; }
    #pragma unroll
    for (int i = 0; i < 2; i++) { int idx = tid + i * 256; rowB[i] = idx >> 3; kqB[i] = idx & 7; }

    // prefetch chunk 0
    #pragma unroll
    for (int i = 0; i < 4; i++) pa[i] = *(const float4*)&X[(m0 + rowA[i]) * 128 + kqA[i] * 4];
    #pragma unroll
    for (int i = 0; i < 2; i++) pb[i] = *(const float4*)&W[(n0 + rowB[i]) * 128 + kqB[i] * 4];

    for (int kc = 0; kc < 4; kc++) {
        #pragma unroll
        for (int i = 0; i < 4; i++) {
            As[kqA[i] * 4 + 0][rowA[i]] = pa[i].x;
            As[kqA[i] * 4 + 1][rowA[i]] = pa[i].y;
            As[kqA[i] * 4 + 2][rowA[i]] = pa[i].z;
            As[kqA[i] * 4 + 3][rowA[i]] = pa[i].w;
        }
        #pragma unroll
        for (int i = 0; i < 2; i++) {
            Bs[kqB[i] * 4 + 0][rowB[i]] = pb[i].x;
            Bs[kqB[i] * 4 + 1][rowB[i]] = pb[i].y;
            Bs[kqB[i] * 4 + 2][rowB[i]] = pb[i].z;
            Bs[kqB[i] * 4 + 3][rowB[i]] = pb[i].w;
        }
        __syncthreads();
        if (kc < 3) {
            int k0 = (kc + 1) * 32;
            #pragma unroll
            for (int i = 0; i < 4; i++) pa[i] = *(const float4*)&X[(m0 + rowA[i]) * 128 + k0 + kqA[i] * 4];
            #pragma unroll
            for (int i = 0; i < 2; i++) pb[i] = *(const float4*)&W[(n0 + rowB[i]) * 128 + k0 + kqB[i] * 4];
        }
        #pragma unroll
        for (int k = 0; k < 32; k++) {
            F4U a0, a1, b;
            a0.f4 = *(const float4*)&As[k][ty * 8];
            a1.f4 = *(const float4*)&As[k][ty * 8 + 4];
            b.f4  = *(const float4*)&Bs[k][tx * 4];
            unsigned long long bd[4];
            #pragma unroll
            for (int c = 0; c < 4; c++) bd[c] = dup2(b.f[c]);
            #pragma unroll
            for (int c = 0; c < 4; c++) {
                ffma2(acc[0][c], a0.u[0], bd[c]);
                ffma2(acc[1][c], a0.u[1], bd[c]);
                ffma2(acc[2][c], a1.u[0], bd[c]);
                ffma2(acc[3][c], a1.u[1], bd[c]);
            }
        }
        __syncthreads();
    }
    float scale = (n0 < 128) ? QSCALE : 1.0f;
    int n = n0 + tx * 4;
    float4 b4 = *(const float4*)&g_bias384[n];
    #pragma unroll
    for (int r2 = 0; r2 < 4; r2++) {
        float2 p0 = unpk2(acc[r2][0]), p1 = unpk2(acc[r2][1]);
        float2 p2 = unpk2(acc[r2][2]), p3 = unpk2(acc[r2][3]);
        int m = m0 + ty * 8 + r2 * 2;
        float4 lo = make_float4((p0.x + b4.x) * scale, (p1.x + b4.y) * scale,
                                (p2.x + b4.z) * scale, (p3.x + b4.w) * scale);
        float4 hi = make_float4((p0.y + b4.x) * scale, (p1.y + b4.y) * scale,
                                (p2.y + b4.z) * scale, (p3.y + b4.w) * scale);
        *(float4*)&g_y[m * 384 + n] = lo;
        *(float4*)&g_y[(m + 1) * 384 + n] = hi;
    }
}

// ---------------- G2: OUT = X @ P1^T + CTX @ Wco^T + bco ----------------
__global__ void __launch_bounds__(256) out_gemm(const float* __restrict__ X,
                                                const float* __restrict__ PW,
                                                float* __restrict__ OUT)
{
    __shared__ float As[32][AS_P];
    __shared__ float Bs[32][BS_P];
    int m0 = blockIdx.x * 128, n0 = blockIdx.y * 64;
    int tid = threadIdx.x, tx = tid & 15, ty = tid >> 4;

    unsigned long long acc[4][4];
    #pragma unroll
    for (int r = 0; r < 4; r++)
        #pragma unroll
        for (int c = 0; c < 4; c++) acc[r][c] = 0ULL;

    float4 pa[4], pb[2];
    int rowA[4], kqA[4], rowB[2], kqB[2];
    #pragma unroll
    for (int i = 0; i < 4; i++) { int idx = tid + i * 256; rowA[i] = idx >> 3; kqA[i] = idx & 7; }
    #pragma unroll
    for (int i = 0; i < 2; i++) { int idx = tid + i * 256; rowB[i] = idx >> 3; kqB[i] = idx & 7; }

    // prefetch kc=0
    #pragma unroll
    for (int i = 0; i < 4; i++) pa[i] = *(const float4*)&X[(m0 + rowA[i]) * 128 + kqA[i] * 4];
    #pragma unroll
    for (int i = 0; i < 2; i++) pb[i] = *(const float4*)&PW[(n0 + rowB[i]) * 256 + kqB[i] * 4];

    for (int kc = 0; kc < 8; kc++) {
        #pragma unroll
        for (int i = 0; i < 4; i++) {
            As[kqA[i] * 4 + 0][rowA[i]] = pa[i].x;
            As[kqA[i] * 4 + 1][rowA[i]] = pa[i].y;
            As[kqA[i] * 4 + 2][rowA[i]] = pa[i].z;
            As[kqA[i] * 4 + 3][rowA[i]] = pa[i].w;
        }
        #pragma unroll
        for (int i = 0; i < 2; i++) {
            Bs[kqB[i] * 4 + 0][rowB[i]] = pb[i].x;
            Bs[kqB[i] * 4 + 1][rowB[i]] = pb[i].y;
            Bs[kqB[i] * 4 + 2][rowB[i]] = pb[i].z;
            Bs[kqB[i] * 4 + 3][rowB[i]] = pb[i].w;
        }
        __syncthreads();
        if (kc < 7) {
            int knext = kc + 1;
            int kcol = (knext & 3) * 32;
            if (knext < 4) {
                #pragma unroll
                for (int i = 0; i < 4; i++) pa[i] = *(const float4*)&X[(m0 + rowA[i]) * 128 + kcol + kqA[i] * 4];
                #pragma unroll
                for (int i = 0; i < 2; i++) pb[i] = *(const float4*)&PW[(n0 + rowB[i]) * 256 + kcol + kqB[i] * 4];
            } else {
                #pragma unroll
                for (int i = 0; i < 4; i++) pa[i] = *(const float4*)&g_ctx[(m0 + rowA[i]) * 128 + kcol + kqA[i] * 4];
                #pragma unroll
                for (int i = 0; i < 2; i++) pb[i] = *(const float4*)&g_wco[(n0 + rowB[i]) * 128 + kcol + kqB[i] * 4];
            }
        }
        #pragma unroll
        for (int k = 0; k < 32; k++) {
            F4U a0, a1, b;
            a0.f4 = *(const float4*)&As[k][ty * 8];
            a1.f4 = *(const float4*)&As[k][ty * 8 + 4];
            b.f4  = *(const float4*)&Bs[k][tx * 4];
            unsigned long long bd[4];
            #pragma unroll
            for (int c = 0; c < 4; c++) bd[c] = dup2(b.f[c]);
            #pragma unroll
            for (int c = 0; c < 4; c++) {
                ffma2(acc[0][c], a0.u[0], bd[c]);
                ffma2(acc[1][c], a0.u[1], bd[c]);
                ffma2(acc[2][c], a1.u[0], bd[c]);
                ffma2(acc[3][c], a1.u[1], bd[c]);
            }
        }
        __syncthreads();
    }
    int n = n0 + tx * 4;
    float4 b4 = *(const float4*)&g_bco[n];
    #pragma unroll
    for (int r2 = 0; r2 < 4; r2++) {
        float2 p0 = unpk2(acc[r2][0]), p1 = unpk2(acc[r2][1]);
        float2 p2 = unpk2(acc[r2][2]), p3 = unpk2(acc[r2][3]);
        int m = m0 + ty * 8 + r2 * 2;
        float4 lo = make_float4(p0.x + b4.x, p1.x + b4.y, p2.x + b4.z, p3.x + b4.w);
        float4 hi = make_float4(p0.y + b4.x, p1.y + b4.y, p2.y + b4.z, p3.y + b4.w);
        *(float4*)&OUT[m * 128 + n] = lo;
        *(float4*)&OUT[(m + 1) * 128 + n] = hi;
    }
}

// ---------------- K3: per-scene attention core ----------------
// smem (floats): Q[64*128]=8192 | KFt[128*66]=8448 | WK2[128*66]=8448 |
//                VFt[128*68]=8704 | WV2[128*68]=8704 | W1B[64*4]=256 | P2[64*2]=128 |
//                Tw[16*256]=4096 | SC[16*256]=4096 | Gw[16*256]=4096   => 55168
#define OFF_KF   8192
#define OFF_WK2  16640
#define OFF_VF   25088
#define OFF_WV2  33792
#define OFF_W1B  42496
#define OFF_P2   42752
#define OFF_TW   42880
#define OFF_SC   46976
#define OFF_GW   51072
#define ATTN_SMEM_FLOATS 55168

__global__ void __launch_bounds__(512) attn_kernel(const float* __restrict__ pos,
                                                   const float* __restrict__ W1,
                                                   const float* __restrict__ b1)
{
    extern __shared__ float sm[];
    float*  Q   = sm;
    float*  KFt = sm + OFF_KF;    // [d][j]  stride 66
    float*  WK2 = sm + OFF_WK2;   // [d][c]  stride 66
    float*  VFt = sm + OFF_VF;    // [vd][j] stride 68
    float*  WV2 = sm + OFF_WV2;   // [vd][c] stride 68
    float4* W1B = (float4*)(sm + OFF_W1B); // (w1x, w1y, b1, 0)
    float2* P2  = (float2*)(sm + OFF_P2);
    float*  Tw  = sm + OFF_TW;    // per-warp [c][h]
    float*  SC  = sm + OFF_SC;    // per-warp [h][j]
    float*  Gw  = sm + OFF_GW;    // per-warp [h][c]

    int s = blockIdx.x, tid = threadIdx.x;
    int w = tid >> 5, lane = tid & 31;
    int base = s * 64;

    #pragma unroll
    for (int it = 0; it < 4; it++) {            // Q: float4 copies
        int idx = tid + it * 512;
        int r = idx >> 5, cq = idx & 31;
        *(float4*)&Q[r * 128 + cq * 4] = *(const float4*)&g_y[(base + r) * 384 + cq * 4];
    }
    #pragma unroll
    for (int it = 0; it < 16; it++) {           // KF,VF transpose (scalar, coalesced LDG)
        int idx = tid + it * 512;
        int r = idx >> 7, c = idx & 127;
        KFt[c * 66 + r] = g_y[(base + r) * 384 + 128 + c];
        VFt[c * 68 + r] = g_y[(base + r) * 384 + 256 + c];
    }
    #pragma unroll
    for (int it = 0; it < 16; it++) {           // WK2 re-strided copy
        int idx = tid + it * 512;
        int row = idx >> 6, c = idx & 63;
        WK2[row * 66 + c] = g_wk2[idx];
    }
    #pragma unroll
    for (int it = 0; it < 4; it++) {            // WV2 float4 re-strided copy
        int idx = tid + it * 512;
        int row = idx >> 4, cq = idx & 15;
        *(float4*)&WV2[row * 68 + cq * 4] = *(const float4*)&g_wv2[row * 64 + cq * 4];
    }
    if (tid < 64) {
        W1B[tid] = make_float4(W1[tid * 2], W1[tid * 2 + 1], b1[tid], 0.f);
        P2[tid]  = *(const float2*)&pos[(base + tid) * 2];
    }
    __syncthreads();

    float* myT  = Tw + w * 256;
    float* mySC = SC + w * 256;
    float* myG  = Gw + w * 256;
    int c0 = 2 * lane, c1 = c0 + 1;     // also j0, j1

    float4 wp0 = W1B[c0], wp1 = W1B[c1];
    float2 pj0 = P2[c0],  pj1 = P2[c1];

    for (int i = w; i < 64; i += 16) {
        const float* qrow = Q + i * 128;
        float2 pi = P2[i];
        float dxj0 = pj0.x - pi.x, dyj0 = pj0.y - pi.y;
        float dxj1 = pj1.x - pi.x, dyj1 = pj1.y - pi.y;

        // ---- merged: t[h][c-pair] and qk-score[h][j-pair] over d ----
        unsigned long long tacc[4], sacc[4];
        #pragma unroll
        for (int h = 0; h < 4; h++) { tacc[h] = 0ULL; sacc[h] = 0ULL; }
        #pragma unroll
        for (int h = 0; h < 4; h++) {
            #pragma unroll
            for (int dq = 0; dq < 8; dq++) {
                int dbase = h * 32 + dq * 4;
                F4U q4; q4.f4 = *(const float4*)&qrow[dbase];
                #pragma unroll
                for (int u = 0; u < 4; u++) {
                    int d = dbase + u;
                    unsigned long long kk = *(const unsigned long long*)&KFt[d * 66 + c0];
                    unsigned long long wk = *(const unsigned long long*)&WK2[d * 66 + c0];
                    unsigned long long qd = dup2(q4.f[u]);
                    ffma2(tacc[h], qd, wk);
                    ffma2(sacc[h], qd, kk);
                }
            }
        }
        float a0[4], a1[4];
        {
            float t0[4], t1[4];
            #pragma unroll
            for (int h = 0; h < 4; h++) {
                float2 tp = unpk2(tacc[h]); t0[h] = tp.x; t1[h] = tp.y;
                float2 sp = unpk2(sacc[h]); a0[h] = sp.x; a1[h] = sp.y;
            }
            *(float4*)&myT[c0 * 4] = make_float4(t0[0], t0[1], t0[2], t0[3]);
            *(float4*)&myT[c1 * 4] = make_float4(t1[0], t1[1], t1[2], t1[3]);
        }
        __syncwarp();

        // ---- rel-encoding contribution to scores ----
        #pragma unroll 8
        for (int c = 0; c < 64; c++) {
            float4 wb = W1B[c];
            float4 tv = *(const float4*)&myT[c * 4];
            float h0 = fmaxf(fmaf(wb.x, dxj0, fmaf(wb.y, dyj0, wb.z)), 0.f);
            float h1 = fmaxf(fmaf(wb.x, dxj1, fmaf(wb.y, dyj1, wb.z)), 0.f);
            a0[0] = fmaf(tv.x, h0, a0[0]); a1[0] = fmaf(tv.x, h1, a1[0]);
            a0[1] = fmaf(tv.y, h0, a0[1]); a1[1] = fmaf(tv.y, h1, a1[1]);
            a0[2] = fmaf(tv.z, h0, a0[2]); a1[2] = fmaf(tv.z, h1, a1[2]);
            a0[3] = fmaf(tv.w, h0, a0[3]); a1[3] = fmaf(tv.w, h1, a1[3]);
        }

        // ---- softmax per head (j pair per lane) ----
        #pragma unroll
        for (int h = 0; h < 4; h++) {
            float m = fmaxf(a0[h], a1[h]);
            #pragma unroll
            for (int off = 16; off; off >>= 1)
                m = fmaxf(m, __shfl_xor_sync(0xffffffffu, m, off));
            float e0 = __expf(a0[h] - m), e1 = __expf(a1[h] - m);
            float ss = e0 + e1;
            #pragma unroll
            for (int off = 16; off; off >>= 1)
                ss += __shfl_xor_sync(0xffffffffu, ss, off);
            float rinv = 1.f / ss;
            *(float2*)&mySC[h * 64 + c0] = make_float2(e0 * rinv, e1 * rinv);
        }
        __syncwarp();

        // ---- g[h][c-pair] = sum_j attn[h][j] * hid[j][c] ----
        {
            float g0[4] = {0, 0, 0, 0}, g1[4] = {0, 0, 0, 0};
            #pragma unroll 4
            for (int j = 0; j < 64; j++) {
                float2 pj = P2[j];
                float dx = pj.x - pi.x, dy = pj.y - pi.y;
                float h0 = fmaxf(fmaf(wp0.x, dx, fmaf(wp0.y, dy, wp0.z)), 0.f);
                float h1 = fmaxf(fmaf(wp1.x, dx, fmaf(wp1.y, dy, wp1.z)), 0.f);
                #pragma unroll
                for (int h = 0; h < 4; h++) {
                    float a = mySC[h * 64 + j];
                    g0[h] = fmaf(a, h0, g0[h]);
                    g1[h] = fmaf(a, h1, g1[h]);
                }
            }
            #pragma unroll
            for (int h = 0; h < 4; h++)
                *(float2*)&myG[h * 64 + c0] = make_float2(g0[h], g1[h]);
        }
        __syncwarp();

        // ---- ctx[i][h*32+lane] = attn@vf + g@Wv2^T ----
        #pragma unroll
        for (int h = 0; h < 4; h++) {
            float acc = 0.f;
            const float* vr = VFt + (h * 32 + lane) * 68;
            const float* ar = mySC + h * 64;
            #pragma unroll
            for (int jq = 0; jq < 16; jq++) {
                float4 av = *(const float4*)&ar[jq * 4];
                float4 vv = *(const float4*)&vr[jq * 4];
                acc = fmaf(av.x, vv.x, acc);
                acc = fmaf(av.y, vv.y, acc);
                acc = fmaf(av.z, vv.z, acc);
                acc = fmaf(av.w, vv.w, acc);
            }
            const float* wr = WV2 + (h * 32 + lane) * 68;
            const float* gr = myG + h * 64;
            #pragma unroll
            for (int cq = 0; cq < 16; cq++) {
                float4 gv = *(const float4*)&gr[cq * 4];
                float4 wv = *(const float4*)&wr[cq * 4];
                acc = fmaf(gv.x, wv.x, acc);
                acc = fmaf(gv.y, wv.y, acc);
                acc = fmaf(gv.z, wv.z, acc);
                acc = fmaf(gv.w, wv.w, acc);
            }
            g_ctx[(base + i) * 128 + h * 32 + lane] = acc;
        }
        __syncwarp();
    }
}

// ---------------- launch ----------------
extern "C" void kernel_launch(void* const* d_in, const int* in_sizes, int n_in,
                              void* d_out, int out_size)
{
    const float* node_features = (const float*)d_in[0];
    const float* positions     = (const float*)d_in[1];
    const float* W1            = (const float*)d_in[2];
    const float* b1            = (const float*)d_in[3];
    const float* W2            = (const float*)d_in[4];
    const float* b2            = (const float*)d_in[5];
    const float* in_proj_w     = (const float*)d_in[6];
    const float* in_proj_b     = (const float*)d_in[7];
    const float* out_w         = (const float*)d_in[8];
    const float* out_b         = (const float*)d_in[9];
    const float* proj_w        = (const float*)d_in[10];
    const float* proj_b        = (const float*)d_in[11];
    float* out = (float*)d_out;

    size_t attn_smem = (size_t)ATTN_SMEM_FLOATS * sizeof(float);
    cudaFuncSetAttribute(attn_kernel, cudaFuncAttributeMaxDynamicSharedMemorySize,
                         (int)attn_smem);

    prep_kernel<<<130, 256>>>(in_proj_w, in_proj_b, W2, b2, out_w, out_b, proj_w, proj_b);
    qkv_gemm<<<dim3(TOTAL / 128, 384 / 64), 256>>>(node_features, in_proj_w);
    attn_kernel<<<S_SCENES, 512, attn_smem>>>(positions, W1, b1);
    out_gemm<<<dim3(TOTAL / 128, 128 / 64), 256>>>(node_features, proj_w, out);
}